// round 6
// baseline (speedup 1.0000x reference)
#include <cuda_runtime.h>
#include <cstddef>

// Problem constants
#define B_ 4096
#define T_ 24
#define I_ 128
#define H_ 512
#define W_ 32
#define BT_ (B_ * T_)

// ---------------------------------------------------------------------------
// Scratch: __device__ globals (the sanctioned no-allocation scratch mechanism).
// Referenced DIRECTLY from device code — no cudaGetSymbolAddress, no static
// constructors, no host-side runtime API anywhere in this file.
// ---------------------------------------------------------------------------
__device__ float g_e    [(size_t)BT_ * H_];   // sigmoid(xw @ w_e^T + b_e), [B*T, H]
__device__ float g_pre_o[(size_t)BT_ * H_];   // [T, B, H]
__device__ float g_pre_r[(size_t)BT_ * H_];   // [T, B, H]
__device__ float g_pre_z[(size_t)BT_ * H_];   // [T, B, H]
__device__ float g_pre_h[(size_t)BT_ * H_];   // [T, B, H]
__device__ float g_ho [(size_t)B_ * H_];
__device__ float g_rho[(size_t)B_ * H_];
__device__ float g_zb [(size_t)B_ * H_];
__device__ float g_h  [(size_t)B_ * H_];

// Scratch ids for the GK_PRE output selector
#define SID_PRE_O 0
#define SID_PRE_R 1
#define SID_PRE_Z 2
#define SID_PRE_H 3

__device__ __forceinline__ float* scratch_out(int id) {
    switch (id) {
        case SID_PRE_O: return g_pre_o;
        case SID_PRE_R: return g_pre_r;
        case SID_PRE_Z: return g_pre_z;
        default:        return g_pre_h;
    }
}

// ---------------------------------------------------------------------------
// Generic NT GEMM: C[m,n] = sum_p sum_k A_p[m - shift_p, k] * W_p[n, k]
// (rows with m - shift_p < 0 read as zero). 128x128 tile, BK=8, 256 threads,
// 8x8 per-thread micro-tile. Epilogue + scratch wiring selected by MODE.
// A source per phase: Aptr[p] if non-null, else the MODE's device-global.
// ---------------------------------------------------------------------------
enum {
    GK_E = 0,       // out: g_e
    GK_PRE = 1,     // out: scratch_out(outId), A null-phase = g_e
    GK_STEP1 = 2,   // A = g_h,  add = g_pre_o+off, out = g_ho
    GK_STEP2R = 3,  // A = g_ho, add = g_pre_r+off, out = g_rho (* g_ho)
    GK_STEP2Z = 4,  // A = g_ho, add = g_pre_z+off, out = g_zb
    GK_STEP3 = 5    // A = g_rho,add = g_pre_h+off, out = g_h and d_out
};

struct GArgs {
    const float* Aptr[3];  // null => MODE-specific device global
    const float* Wt[3];
    int K[3];
    int shift[3];
    int nph;
    const float* bias;     // may be null
    int outId;             // GK_PRE only
    float* out2;           // d_out (GK_STEP3 only)
    int t;                 // recurrence step (offsets into pre_* and d_out)
};

__device__ __forceinline__ float sigmoidf_(float x) {
    return 1.0f / (1.0f + __expf(-x));
}

template <int MODE>
__global__ void __launch_bounds__(256) gemm_k(GArgs g) {
    __shared__ float As[8][128];
    __shared__ float Ws[8][128];

    const int tid = threadIdx.x;
    const int rowBase = blockIdx.y * 128;
    const int colBase = blockIdx.x * 128;

    float acc[8][8];
#pragma unroll
    for (int i = 0; i < 8; i++)
#pragma unroll
        for (int j = 0; j < 8; j++) acc[i][j] = 0.0f;

    const int ldRow = tid >> 1;          // 0..127
    const int ldCol = (tid & 1) << 2;    // 0 or 4
    const int ty = tid >> 4;             // 0..15
    const int tx = tid & 15;             // 0..15

    for (int p = 0; p < g.nph; p++) {
        const float* A = g.Aptr[p];
        if (A == nullptr) {
            // MODE-specific device-global A source
            if (MODE == GK_PRE)        A = g_e;
            else if (MODE == GK_STEP1) A = g_h;
            else if (MODE == GK_STEP2R || MODE == GK_STEP2Z) A = g_ho;
            else                       A = g_rho;   // GK_STEP3
        }
        const float* __restrict__ W = g.Wt[p];
        const int K = g.K[p];
        const int sh = g.shift[p];

        for (int k0 = 0; k0 < K; k0 += 8) {
            // Load A tile (zero rows for shifted-out-of-range sources)
            const int srow = rowBase + ldRow - sh;
            float4 av = make_float4(0.f, 0.f, 0.f, 0.f);
            if (srow >= 0)
                av = *reinterpret_cast<const float4*>(A + (size_t)srow * K + k0 + ldCol);
            As[ldCol + 0][ldRow] = av.x;
            As[ldCol + 1][ldRow] = av.y;
            As[ldCol + 2][ldRow] = av.z;
            As[ldCol + 3][ldRow] = av.w;

            // Load W tile
            const float4 wv = *reinterpret_cast<const float4*>(
                W + (size_t)(colBase + ldRow) * K + k0 + ldCol);
            Ws[ldCol + 0][ldRow] = wv.x;
            Ws[ldCol + 1][ldRow] = wv.y;
            Ws[ldCol + 2][ldRow] = wv.z;
            Ws[ldCol + 3][ldRow] = wv.w;

            __syncthreads();

#pragma unroll
            for (int kk = 0; kk < 8; kk++) {
                float af[8], bf[8];
#pragma unroll
                for (int i = 0; i < 8; i++) af[i] = As[kk][ty * 8 + i];
#pragma unroll
                for (int j = 0; j < 8; j++) bf[j] = Ws[kk][tx * 8 + j];
#pragma unroll
                for (int i = 0; i < 8; i++)
#pragma unroll
                    for (int j = 0; j < 8; j++) acc[i][j] += af[i] * bf[j];
            }
            __syncthreads();
        }
    }

    // Epilogue
    const size_t off = (size_t)g.t * B_ * H_;
    const int mBase = rowBase + ty * 8;
    const int nBase = colBase + tx * 8;
#pragma unroll
    for (int i = 0; i < 8; i++) {
        const int m = mBase + i;
        const int b_row = m / T_;          // hoisted for GK_PRE transpose-store
        const int t_row = m - b_row * T_;
#pragma unroll
        for (int j = 0; j < 8; j++) {
            const int n = nBase + j;
            float v = acc[i][j];
            if (MODE == GK_E) {
                v += g.bias[n];
                g_e[(size_t)m * H_ + n] = sigmoidf_(v);
            } else if (MODE == GK_PRE) {
                if (g.bias) v += g.bias[n];
                scratch_out(g.outId)[((size_t)t_row * B_ + b_row) * H_ + n] = v;
            } else if (MODE == GK_STEP1) {
                const size_t idx = (size_t)m * H_ + n;
                v += g_pre_o[off + idx];
                g_ho[idx] = sigmoidf_(v);
            } else if (MODE == GK_STEP2R) {
                const size_t idx = (size_t)m * H_ + n;
                v += g_pre_r[off + idx];
                g_rho[idx] = sigmoidf_(v) * g_ho[idx];
            } else if (MODE == GK_STEP2Z) {
                const size_t idx = (size_t)m * H_ + n;
                v += g_pre_z[off + idx];
                g_zb[idx] = sigmoidf_(v);
            } else {  // GK_STEP3
                const size_t idx = (size_t)m * H_ + n;
                v += g_pre_h[off + idx];
                const float ht = tanhf(v);
                const float z = g_zb[idx];
                const float ho = g_ho[idx];
                const float h = (1.0f - z) * ho + z * ht;
                g_h[idx] = h;
                g.out2[((size_t)m * T_ + g.t) * H_ + n] = h;
            }
        }
    }
}

// ---------------------------------------------------------------------------
// Host launch — kernel launches ONLY. No runtime API calls of any kind.
// ---------------------------------------------------------------------------
extern "C" void kernel_launch(void* const* d_in, const int* in_sizes, int n_in,
                              void* d_out, int out_size) {
    (void)in_sizes; (void)n_in; (void)out_size;

    const float* x    = (const float*)d_in[0];
    const float* xw   = (const float*)d_in[1];
    const float* w_rx = (const float*)d_in[2];
    const float* w_rh = (const float*)d_in[3];
    const float* w_re = (const float*)d_in[4];
    const float* b_r  = (const float*)d_in[5];
    const float* w_zx = (const float*)d_in[6];
    const float* w_zh = (const float*)d_in[7];
    const float* w_ze = (const float*)d_in[8];
    const float* b_z  = (const float*)d_in[9];
    const float* w_hx = (const float*)d_in[10];
    const float* w_hh = (const float*)d_in[11];
    const float* b_h  = (const float*)d_in[12];
    const float* w_d  = (const float*)d_in[13];
    const float* w_w  = (const float*)d_in[14];
    const float* w_m  = (const float*)d_in[15];
    const float* w_t  = (const float*)d_in[16];
    const float* w_e  = (const float*)d_in[17];
    const float* b_e  = (const float*)d_in[18];
    float* out = (float*)d_out;

    const dim3 blk(256);
    const dim3 gridPre(H_ / 128, BT_ / 128);   // 4 x 768
    const dim3 gridStep(H_ / 128, B_ / 128);   // 4 x 32

    // ---- e = sigmoid(xw @ w_e^T + b_e), [B*T, H] flat -> g_e
    {
        GArgs a = {};
        a.Aptr[0] = xw; a.Wt[0] = w_e; a.K[0] = W_; a.shift[0] = 0;
        a.nph = 1; a.bias = b_e;
        gemm_k<GK_E><<<gridPre, blk>>>(a);
    }
    // ---- pre_r = x @ w_rx^T + e @ w_re^T + b_r  -> [T,B,H] g_pre_r
    {
        GArgs a = {};
        a.Aptr[0] = x;       a.Wt[0] = w_rx; a.K[0] = I_; a.shift[0] = 0;
        a.Aptr[1] = nullptr; a.Wt[1] = w_re; a.K[1] = H_; a.shift[1] = 0;  // A = g_e
        a.nph = 2; a.bias = b_r; a.outId = SID_PRE_R;
        gemm_k<GK_PRE><<<gridPre, blk>>>(a);
    }
    // ---- pre_z = x @ w_zx^T + e @ w_ze^T + b_z  -> [T,B,H] g_pre_z
    {
        GArgs a = {};
        a.Aptr[0] = x;       a.Wt[0] = w_zx; a.K[0] = I_; a.shift[0] = 0;
        a.Aptr[1] = nullptr; a.Wt[1] = w_ze; a.K[1] = H_; a.shift[1] = 0;  // A = g_e
        a.nph = 2; a.bias = b_z; a.outId = SID_PRE_Z;
        gemm_k<GK_PRE><<<gridPre, blk>>>(a);
    }
    // ---- pre_h = x @ w_hx^T + b_h  -> [T,B,H] g_pre_h
    {
        GArgs a = {};
        a.Aptr[0] = x; a.Wt[0] = w_hx; a.K[0] = I_; a.shift[0] = 0;
        a.nph = 1; a.bias = b_h; a.outId = SID_PRE_H;
        gemm_k<GK_PRE><<<gridPre, blk>>>(a);
    }
    // ---- pre_o = shift1(x)@w_d^T + shift7(x)@w_w^T + shift30(x)@w_m^T -> g_pre_o
    //      (reference shifts along the BATCH axis: row m sources row m - k*T)
    {
        GArgs a = {};
        a.Aptr[0] = x; a.Wt[0] = w_d; a.K[0] = I_; a.shift[0] = 1 * T_;
        a.Aptr[1] = x; a.Wt[1] = w_w; a.K[1] = I_; a.shift[1] = 7 * T_;
        a.Aptr[2] = x; a.Wt[2] = w_m; a.K[2] = I_; a.shift[2] = 30 * T_;
        a.nph = 3; a.bias = nullptr; a.outId = SID_PRE_O;
        gemm_k<GK_PRE><<<gridPre, blk>>>(a);
    }

    // ---- recurrence over T steps
    for (int t = 0; t < T_; t++) {
        // h_o = sigmoid(pre_o_t + h @ w_t^T); at t=0 h=0 (shift=B_ zeroes all A rows)
        {
            GArgs a = {};
            a.Aptr[0] = nullptr;  // A = g_h
            a.Wt[0] = w_t; a.K[0] = H_;
            a.shift[0] = (t == 0) ? B_ : 0;
            a.nph = 1; a.t = t;
            gemm_k<GK_STEP1><<<gridStep, blk>>>(a);
        }
        // r*h_o = sigmoid(pre_r_t + h_o @ w_rh^T) * h_o
        {
            GArgs a = {};
            a.Aptr[0] = nullptr;  // A = g_ho
            a.Wt[0] = w_rh; a.K[0] = H_; a.shift[0] = 0;
            a.nph = 1; a.t = t;
            gemm_k<GK_STEP2R><<<gridStep, blk>>>(a);
        }
        // z = sigmoid(pre_z_t + h_o @ w_zh^T)
        {
            GArgs a = {};
            a.Aptr[0] = nullptr;  // A = g_ho
            a.Wt[0] = w_zh; a.K[0] = H_; a.shift[0] = 0;
            a.nph = 1; a.t = t;
            gemm_k<GK_STEP2Z><<<gridStep, blk>>>(a);
        }
        // h = (1-z)*h_o + z*tanh(pre_h_t + (r*h_o) @ w_hh^T); -> g_h and d_out[:,t,:]
        {
            GArgs a = {};
            a.Aptr[0] = nullptr;  // A = g_rho
            a.Wt[0] = w_hh; a.K[0] = H_; a.shift[0] = 0;
            a.nph = 1; a.t = t; a.out2 = out;
            gemm_k<GK_STEP3><<<gridStep, blk>>>(a);
        }
    }
}

// round 7
// speedup vs baseline: 1.1622x; 1.1622x over previous
#include <cuda_runtime.h>
#include <cstddef>
#include <cstdint>

// Problem constants
#define B_ 4096
#define T_ 24
#define I_ 128
#define H_ 512
#define W_ 32
#define BT_ (B_ * T_)

// ---------------------------------------------------------------------------
// Scratch: __device__ globals, referenced directly from device code.
// ---------------------------------------------------------------------------
__device__ float g_e    [(size_t)BT_ * H_];   // sigmoid(xw @ w_e^T + b_e), [B*T, H]
__device__ float g_pre_o[(size_t)BT_ * H_];   // [T, B, H]
__device__ float g_pre_r[(size_t)BT_ * H_];   // [T, B, H]
__device__ float g_pre_z[(size_t)BT_ * H_];   // [T, B, H]
__device__ float g_pre_h[(size_t)BT_ * H_];   // [T, B, H]
__device__ float g_ho [(size_t)B_ * H_];
__device__ float g_rho[(size_t)B_ * H_];
__device__ float g_zb [(size_t)B_ * H_];
__device__ float g_h  [(size_t)B_ * H_];

#define SID_PRE_O 0
#define SID_PRE_R 1
#define SID_PRE_Z 2
#define SID_PRE_H 3

__device__ __forceinline__ float* scratch_out(int id) {
    switch (id) {
        case SID_PRE_O: return g_pre_o;
        case SID_PRE_R: return g_pre_r;
        case SID_PRE_Z: return g_pre_z;
        default:        return g_pre_h;
    }
}

// Epilogue / wiring modes
enum {
    GK_E = 0,        // out: g_e
    GK_PRE = 1,      // out: scratch_out(outId); A null-phase = g_e
    GK_STEP1 = 2,    // A = g_h,  add = g_pre_o+off, out = g_ho
    GK_STEP2RZ = 3,  // A = g_ho; blockIdx.x<4: r-path (w_rh), else z-path (w_zh)
    GK_STEP3 = 4     // A = g_rho, add = g_pre_h+off, out = g_h and d_out
};

struct GArgs {
    const float* Aptr[3];  // null => MODE-specific device global
    const float* Wt[3];    // for GK_STEP2RZ: Wt[0]=w_rh, Wt[1]=w_zh
    int K[3];
    int shift[3];
    int nph;
    const float* bias;     // may be null
    int outId;             // GK_PRE only
    float* out2;           // d_out (GK_STEP3 only)
    int t;                 // recurrence step
};

__device__ __forceinline__ float sigmoidf_(float x) {
    return 1.0f / (1.0f + __expf(-x));
}

__device__ __forceinline__ uint32_t f2tf32(float x) {
    uint32_t r;
    asm("cvt.rna.tf32.f32 %0, %1;" : "=r"(r) : "f"(x));
    return r;
}

// Split fp32 -> (tf32 hi, tf32 lo) with x ~= hi + lo
__device__ __forceinline__ void tf32_split(float x, uint32_t& hi, uint32_t& lo) {
    hi = f2tf32(x);
    const float hf = __uint_as_float(hi);
    lo = f2tf32(x - hf);
}

__device__ __forceinline__ void mma_tf32(float c[4],
                                         uint32_t a0, uint32_t a1, uint32_t a2, uint32_t a3,
                                         uint32_t b0, uint32_t b1) {
    asm volatile(
        "mma.sync.aligned.m16n8k8.row.col.f32.tf32.tf32.f32 "
        "{%0,%1,%2,%3}, {%4,%5,%6,%7}, {%8,%9}, {%0,%1,%2,%3};"
        : "+f"(c[0]), "+f"(c[1]), "+f"(c[2]), "+f"(c[3])
        : "r"(a0), "r"(a1), "r"(a2), "r"(a3), "r"(b0), "r"(b1));
}

// ---------------------------------------------------------------------------
// TF32x3 tensor-core NT GEMM:
//   C[m,n] = sum_p sum_k A_p[m - shift_p, k] * W_p[n, k]
// Tile: BM x 128, BK=16. 256 threads = 8 warps (2 x 4), warp tile (BM/2) x 32.
// fp32-grade accuracy via hi*hi + lo*hi + hi*lo.
// ---------------------------------------------------------------------------
#define BN 128
#define BK 16
#define BKP 20   // padded k-stride (bank-conflict-free fragment loads)

template <int MODE, int BM>
__global__ void __launch_bounds__(256) gemm_t(GArgs g) {
    __shared__ uint32_t Ahi[BM][BKP];
    __shared__ uint32_t Alo[BM][BKP];
    __shared__ uint32_t Bhi[BN][BKP];
    __shared__ uint32_t Blo[BN][BKP];

    const int tid = threadIdx.x;
    const int lane = tid & 31;
    const int warp = tid >> 5;
    const int qr = lane >> 2;   // 0..7
    const int qc = lane & 3;    // 0..3

    const int rowBase = blockIdx.y * BM;
    const int xblk = (MODE == GK_STEP2RZ) ? (blockIdx.x & 3) : blockIdx.x;
    const int zhalf = (MODE == GK_STEP2RZ) ? (blockIdx.x >> 2) : 0;
    const int colBase = xblk * BN;

    constexpr int WM = BM / 2;        // warp M extent
    constexpr int MF = WM / 16;       // m16 fragments per warp (4 or 2)
    constexpr int NF = 4;             // n8 fragments per warp (WN=32)
    const int warpM = (warp & 1) * WM;
    const int warpN = (warp >> 1) * 32;

    float acc[MF][NF][4];
#pragma unroll
    for (int i = 0; i < MF; i++)
#pragma unroll
        for (int j = 0; j < NF; j++)
#pragma unroll
            for (int r = 0; r < 4; r++) acc[i][j][r] = 0.0f;

    for (int p = 0; p < g.nph; p++) {
        const float* A = g.Aptr[p];
        if (A == nullptr) {
            if (MODE == GK_PRE)          A = g_e;
            else if (MODE == GK_STEP1)   A = g_h;
            else if (MODE == GK_STEP2RZ) A = g_ho;
            else                         A = g_rho;   // GK_STEP3
        }
        const float* __restrict__ W =
            (MODE == GK_STEP2RZ) ? g.Wt[zhalf] : g.Wt[p];
        const int K = g.K[p];
        const int sh = g.shift[p];

        for (int k0 = 0; k0 < K; k0 += BK) {
            // ---- load A tile (BM x 16) as float4, split to tf32 hi/lo
#pragma unroll
            for (int idx = tid; idx < BM * 4; idx += 256) {
                const int row = idx >> 2;
                const int kq = (idx & 3) << 2;
                const int srow = rowBase + row - sh;
                float4 v = make_float4(0.f, 0.f, 0.f, 0.f);
                if (srow >= 0)
                    v = *reinterpret_cast<const float4*>(A + (size_t)srow * K + k0 + kq);
                float vv[4] = {v.x, v.y, v.z, v.w};
#pragma unroll
                for (int j = 0; j < 4; j++) {
                    uint32_t h, l;
                    tf32_split(vv[j], h, l);
                    Ahi[row][kq + j] = h;
                    Alo[row][kq + j] = l;
                }
            }
            // ---- load W tile (128 x 16)
#pragma unroll
            for (int idx = tid; idx < BN * 4; idx += 256) {
                const int row = idx >> 2;
                const int kq = (idx & 3) << 2;
                const float4 v = *reinterpret_cast<const float4*>(
                    W + (size_t)(colBase + row) * K + k0 + kq);
                float vv[4] = {v.x, v.y, v.z, v.w};
#pragma unroll
                for (int j = 0; j < 4; j++) {
                    uint32_t h, l;
                    tf32_split(vv[j], h, l);
                    Bhi[row][kq + j] = h;
                    Blo[row][kq + j] = l;
                }
            }
            __syncthreads();

            // ---- compute: two k8 sub-steps
#pragma unroll
            for (int kk = 0; kk < BK; kk += 8) {
                // B fragments for this warp
                uint32_t bh0[NF], bh1[NF], bl0[NF], bl1[NF];
#pragma unroll
                for (int nf = 0; nf < NF; nf++) {
                    const int brow = warpN + nf * 8 + qr;
                    bh0[nf] = Bhi[brow][kk + qc];
                    bh1[nf] = Bhi[brow][kk + qc + 4];
                    bl0[nf] = Blo[brow][kk + qc];
                    bl1[nf] = Blo[brow][kk + qc + 4];
                }
#pragma unroll
                for (int mf = 0; mf < MF; mf++) {
                    const int ar0 = warpM + mf * 16 + qr;
                    const uint32_t ah0 = Ahi[ar0][kk + qc];
                    const uint32_t ah1 = Ahi[ar0 + 8][kk + qc];
                    const uint32_t ah2 = Ahi[ar0][kk + qc + 4];
                    const uint32_t ah3 = Ahi[ar0 + 8][kk + qc + 4];
                    const uint32_t al0 = Alo[ar0][kk + qc];
                    const uint32_t al1 = Alo[ar0 + 8][kk + qc];
                    const uint32_t al2 = Alo[ar0][kk + qc + 4];
                    const uint32_t al3 = Alo[ar0 + 8][kk + qc + 4];
#pragma unroll
                    for (int nf = 0; nf < NF; nf++) {
                        mma_tf32(acc[mf][nf], ah0, ah1, ah2, ah3, bh0[nf], bh1[nf]);
                        mma_tf32(acc[mf][nf], al0, al1, al2, al3, bh0[nf], bh1[nf]);
                        mma_tf32(acc[mf][nf], ah0, ah1, ah2, ah3, bl0[nf], bl1[nf]);
                    }
                }
            }
            __syncthreads();
        }
    }

    // ---- epilogue
    const size_t off = (size_t)g.t * B_ * H_;
#pragma unroll
    for (int mf = 0; mf < MF; mf++) {
#pragma unroll
        for (int nf = 0; nf < NF; nf++) {
#pragma unroll
            for (int r = 0; r < 4; r++) {
                const int m = rowBase + warpM + mf * 16 + qr + ((r >= 2) ? 8 : 0);
                const int n = colBase + warpN + nf * 8 + qc * 2 + (r & 1);
                float v = acc[mf][nf][r];
                if (MODE == GK_E) {
                    v += g.bias[n];
                    g_e[(size_t)m * H_ + n] = sigmoidf_(v);
                } else if (MODE == GK_PRE) {
                    if (g.bias) v += g.bias[n];
                    const int b_row = m / T_;
                    const int t_row = m - b_row * T_;
                    scratch_out(g.outId)[((size_t)t_row * B_ + b_row) * H_ + n] = v;
                } else if (MODE == GK_STEP1) {
                    const size_t idx = (size_t)m * H_ + n;
                    v += g_pre_o[off + idx];
                    g_ho[idx] = sigmoidf_(v);
                } else if (MODE == GK_STEP2RZ) {
                    const size_t idx = (size_t)m * H_ + n;
                    if (zhalf == 0) {
                        v += g_pre_r[off + idx];
                        g_rho[idx] = sigmoidf_(v) * g_ho[idx];
                    } else {
                        v += g_pre_z[off + idx];
                        g_zb[idx] = sigmoidf_(v);
                    }
                } else {  // GK_STEP3
                    const size_t idx = (size_t)m * H_ + n;
                    v += g_pre_h[off + idx];
                    const float ht = tanhf(v);
                    const float z = g_zb[idx];
                    const float ho = g_ho[idx];
                    const float h = (1.0f - z) * ho + z * ht;
                    g_h[idx] = h;
                    g.out2[((size_t)m * T_ + g.t) * H_ + n] = h;
                }
            }
        }
    }
}

// ---------------------------------------------------------------------------
// Host launch — kernel launches ONLY.
// ---------------------------------------------------------------------------
extern "C" void kernel_launch(void* const* d_in, const int* in_sizes, int n_in,
                              void* d_out, int out_size) {
    (void)in_sizes; (void)n_in; (void)out_size;

    const float* x    = (const float*)d_in[0];
    const float* xw   = (const float*)d_in[1];
    const float* w_rx = (const float*)d_in[2];
    const float* w_rh = (const float*)d_in[3];
    const float* w_re = (const float*)d_in[4];
    const float* b_r  = (const float*)d_in[5];
    const float* w_zx = (const float*)d_in[6];
    const float* w_zh = (const float*)d_in[7];
    const float* w_ze = (const float*)d_in[8];
    const float* b_z  = (const float*)d_in[9];
    const float* w_hx = (const float*)d_in[10];
    const float* w_hh = (const float*)d_in[11];
    const float* b_h  = (const float*)d_in[12];
    const float* w_d  = (const float*)d_in[13];
    const float* w_w  = (const float*)d_in[14];
    const float* w_m  = (const float*)d_in[15];
    const float* w_t  = (const float*)d_in[16];
    const float* w_e  = (const float*)d_in[17];
    const float* b_e  = (const float*)d_in[18];
    float* out = (float*)d_out;

    const dim3 blk(256);
    const dim3 gridPre(H_ / BN, BT_ / 128);     // 4 x 768 (BM=128)
    const dim3 gridStep(H_ / BN, B_ / 64);      // 4 x 64  (BM=64)
    const dim3 gridStepRZ(2 * (H_ / BN), B_ / 64);  // 8 x 64

    // ---- e = sigmoid(xw @ w_e^T + b_e) -> g_e
    {
        GArgs a = {};
        a.Aptr[0] = xw; a.Wt[0] = w_e; a.K[0] = W_; a.shift[0] = 0;
        a.nph = 1; a.bias = b_e;
        gemm_t<GK_E, 128><<<gridPre, blk>>>(a);
    }
    // ---- pre_r = x @ w_rx^T + e @ w_re^T + b_r -> g_pre_r [T,B,H]
    {
        GArgs a = {};
        a.Aptr[0] = x;       a.Wt[0] = w_rx; a.K[0] = I_; a.shift[0] = 0;
        a.Aptr[1] = nullptr; a.Wt[1] = w_re; a.K[1] = H_; a.shift[1] = 0;  // A = g_e
        a.nph = 2; a.bias = b_r; a.outId = SID_PRE_R;
        gemm_t<GK_PRE, 128><<<gridPre, blk>>>(a);
    }
    // ---- pre_z = x @ w_zx^T + e @ w_ze^T + b_z -> g_pre_z [T,B,H]
    {
        GArgs a = {};
        a.Aptr[0] = x;       a.Wt[0] = w_zx; a.K[0] = I_; a.shift[0] = 0;
        a.Aptr[1] = nullptr; a.Wt[1] = w_ze; a.K[1] = H_; a.shift[1] = 0;  // A = g_e
        a.nph = 2; a.bias = b_z; a.outId = SID_PRE_Z;
        gemm_t<GK_PRE, 128><<<gridPre, blk>>>(a);
    }
    // ---- pre_h = x @ w_hx^T + b_h -> g_pre_h [T,B,H]
    {
        GArgs a = {};
        a.Aptr[0] = x; a.Wt[0] = w_hx; a.K[0] = I_; a.shift[0] = 0;
        a.nph = 1; a.bias = b_h; a.outId = SID_PRE_H;
        gemm_t<GK_PRE, 128><<<gridPre, blk>>>(a);
    }
    // ---- pre_o = shift1(x)@w_d^T + shift7(x)@w_w^T + shift30(x)@w_m^T -> g_pre_o
    //      (reference shifts along the BATCH axis: row m sources row m - k*T)
    {
        GArgs a = {};
        a.Aptr[0] = x; a.Wt[0] = w_d; a.K[0] = I_; a.shift[0] = 1 * T_;
        a.Aptr[1] = x; a.Wt[1] = w_w; a.K[1] = I_; a.shift[1] = 7 * T_;
        a.Aptr[2] = x; a.Wt[2] = w_m; a.K[2] = I_; a.shift[2] = 30 * T_;
        a.nph = 3; a.bias = nullptr; a.outId = SID_PRE_O;
        gemm_t<GK_PRE, 128><<<gridPre, blk>>>(a);
    }

    // ---- recurrence over T steps (3 launches per step)
    for (int t = 0; t < T_; t++) {
        // h_o = sigmoid(pre_o_t + h @ w_t^T); t=0 h=0 via shift=B_ (all rows zero)
        {
            GArgs a = {};
            a.Aptr[0] = nullptr;  // A = g_h
            a.Wt[0] = w_t; a.K[0] = H_;
            a.shift[0] = (t == 0) ? B_ : 0;
            a.nph = 1; a.t = t;
            gemm_t<GK_STEP1, 64><<<gridStep, blk>>>(a);
        }
        // fused: r*h_o = sigmoid(pre_r_t + h_o @ w_rh^T) * h_o  (blocks x<4)
        //        z     = sigmoid(pre_z_t + h_o @ w_zh^T)        (blocks x>=4)
        {
            GArgs a = {};
            a.Aptr[0] = nullptr;  // A = g_ho
            a.Wt[0] = w_rh; a.Wt[1] = w_zh;
            a.K[0] = H_; a.shift[0] = 0;
            a.nph = 1; a.t = t;
            gemm_t<GK_STEP2RZ, 64><<<gridStepRZ, blk>>>(a);
        }
        // h = (1-z)*h_o + z*tanh(pre_h_t + (r*h_o) @ w_hh^T) -> g_h, d_out[:,t,:]
        {
            GArgs a = {};
            a.Aptr[0] = nullptr;  // A = g_rho
            a.Wt[0] = w_hh; a.K[0] = H_; a.shift[0] = 0;
            a.nph = 1; a.t = t; a.out2 = out;
            gemm_t<GK_STEP3, 64><<<gridStep, blk>>>(a);
        }
    }
}

// round 8
// speedup vs baseline: 1.2775x; 1.0992x over previous
#include <cuda_runtime.h>
#include <cstddef>
#include <cstdint>

// Problem constants
#define B_ 4096
#define T_ 24
#define I_ 128
#define H_ 512
#define W_ 32
#define BT_ (B_ * T_)

// ---------------------------------------------------------------------------
// Weight split-buffer segment offsets (elements)
// ---------------------------------------------------------------------------
#define SZ_WE   (H_ * W_)
#define SZ_HI   (H_ * I_)
#define SZ_HH   (H_ * H_)
#define OFF_WE  0
#define OFF_WRX (OFF_WE  + SZ_WE)
#define OFF_WZX (OFF_WRX + SZ_HI)
#define OFF_WHX (OFF_WZX + SZ_HI)
#define OFF_WD  (OFF_WHX + SZ_HI)
#define OFF_WW  (OFF_WD  + SZ_HI)
#define OFF_WM  (OFF_WW  + SZ_HI)
#define OFF_WRE (OFF_WM  + SZ_HI)
#define OFF_WZE (OFF_WRE + SZ_HH)
#define OFF_WRH (OFF_WZE + SZ_HH)
#define OFF_WZH (OFF_WRH + SZ_HH)
#define OFF_WHH (OFF_WZH + SZ_HH)
#define OFF_WT  (OFF_WHH + SZ_HH)
#define W_TOTAL (OFF_WT  + SZ_HH)

// ---------------------------------------------------------------------------
// Scratch: __device__ globals only (sanctioned no-allocation scratch).
// hi/lo = tf32 split pairs (uint32 bit patterns).
// ---------------------------------------------------------------------------
__device__ uint32_t g_w_hi[W_TOTAL];
__device__ uint32_t g_w_lo[W_TOTAL];
__device__ uint32_t g_x_hi [(size_t)BT_ * I_];
__device__ uint32_t g_x_lo [(size_t)BT_ * I_];
__device__ uint32_t g_xw_hi[(size_t)BT_ * W_];
__device__ uint32_t g_xw_lo[(size_t)BT_ * W_];
__device__ uint32_t g_e_hi [(size_t)BT_ * H_];
__device__ uint32_t g_e_lo [(size_t)BT_ * H_];
__device__ uint32_t g_h_hi [(size_t)B_ * H_];
__device__ uint32_t g_h_lo [(size_t)B_ * H_];
__device__ uint32_t g_ho_hi[(size_t)B_ * H_];
__device__ uint32_t g_ho_lo[(size_t)B_ * H_];
__device__ uint32_t g_rho_hi[(size_t)B_ * H_];
__device__ uint32_t g_rho_lo[(size_t)B_ * H_];

__device__ float g_pre_o[(size_t)BT_ * H_];   // [T, B, H]
__device__ float g_pre_r[(size_t)BT_ * H_];   // [T, B, H]
__device__ float g_pre_z[(size_t)BT_ * H_];   // [T, B, H]
__device__ float g_pre_h[(size_t)BT_ * H_];   // [T, B, H]
__device__ float g_ho [(size_t)B_ * H_];      // fp32 h_o (epilogue consumer)
__device__ float g_zb [(size_t)B_ * H_];      // fp32 z

// ---------------------------------------------------------------------------
// Helpers
// ---------------------------------------------------------------------------
__device__ __forceinline__ float sigmoidf_(float x) {
    return 1.0f / (1.0f + __expf(-x));
}
__device__ __forceinline__ uint32_t f2tf32(float x) {
    uint32_t r;
    asm("cvt.rna.tf32.f32 %0, %1;" : "=r"(r) : "f"(x));
    return r;
}
__device__ __forceinline__ void tf32_split(float x, uint32_t& hi, uint32_t& lo) {
    hi = f2tf32(x);
    lo = f2tf32(x - __uint_as_float(hi));
}
__device__ __forceinline__ void mma_tf32(float c[4],
                                         uint32_t a0, uint32_t a1, uint32_t a2, uint32_t a3,
                                         uint32_t b0, uint32_t b1) {
    asm volatile(
        "mma.sync.aligned.m16n8k8.row.col.f32.tf32.tf32.f32 "
        "{%0,%1,%2,%3}, {%4,%5,%6,%7}, {%8,%9}, {%0,%1,%2,%3};"
        : "+f"(c[0]), "+f"(c[1]), "+f"(c[2]), "+f"(c[3])
        : "r"(a0), "r"(a1), "r"(a2), "r"(a3), "r"(b0), "r"(b1));
}
__device__ __forceinline__ uint32_t cvta_s(const void* p) {
    return (uint32_t)__cvta_generic_to_shared(p);
}
__device__ __forceinline__ void cp16(uint32_t saddr, const void* gaddr, int src_bytes) {
    asm volatile("cp.async.ca.shared.global [%0], [%1], 16, %2;"
                 :: "r"(saddr), "l"(gaddr), "r"(src_bytes));
}
#define CP_COMMIT() asm volatile("cp.async.commit_group;")
template <int N>
__device__ __forceinline__ void cp_wait() {
    asm volatile("cp.async.wait_group %0;" :: "n"(N));
}

// ---------------------------------------------------------------------------
// Split kernels (run once per kernel_launch, before the GEMMs)
// ---------------------------------------------------------------------------
struct SplitWArgs {
    const float* src[13];
    int sz[13];
    int off[13];
};
__global__ void split_w_k(SplitWArgs a) {
    const int seg = blockIdx.y;
    const int n = a.sz[seg];
    const float* __restrict__ s = a.src[seg];
    const int off = a.off[seg];
    for (int i = blockIdx.x * blockDim.x + threadIdx.x; i < n;
         i += gridDim.x * blockDim.x) {
        uint32_t h, l;
        tf32_split(s[i], h, l);
        g_w_hi[off + i] = h;
        g_w_lo[off + i] = l;
    }
}
__global__ void split_x_k(const float* __restrict__ x, const float* __restrict__ xw) {
    if (blockIdx.y == 0) {
        const size_t n = (size_t)BT_ * I_;
        for (size_t i = blockIdx.x * blockDim.x + threadIdx.x; i < n;
             i += (size_t)gridDim.x * blockDim.x) {
            uint32_t h, l;
            tf32_split(x[i], h, l);
            g_x_hi[i] = h;
            g_x_lo[i] = l;
        }
    } else {
        const size_t n = (size_t)BT_ * W_;
        for (size_t i = blockIdx.x * blockDim.x + threadIdx.x; i < n;
             i += (size_t)gridDim.x * blockDim.x) {
            uint32_t h, l;
            tf32_split(xw[i], h, l);
            g_xw_hi[i] = h;
            g_xw_lo[i] = l;
        }
    }
}

// ---------------------------------------------------------------------------
// GEMM modes / args
// ---------------------------------------------------------------------------
enum { GK_E = 0, GK_PRE = 1, GK_STEP1 = 2, GK_STEP2RZ = 3, GK_STEP3 = 4 };
enum { AS_X = 0, AS_XW = 1, AS_E = 2, AS_H = 3, AS_HO = 4, AS_RHO = 5 };
#define SID_PRE_O 0
#define SID_PRE_R 1
#define SID_PRE_Z 2
#define SID_PRE_H 3

__device__ __forceinline__ float* scratch_out(int id) {
    switch (id) {
        case SID_PRE_O: return g_pre_o;
        case SID_PRE_R: return g_pre_r;
        case SID_PRE_Z: return g_pre_z;
        default:        return g_pre_h;
    }
}
__device__ __forceinline__ void a_src(int id, const uint32_t*& hi, const uint32_t*& lo) {
    switch (id) {
        case AS_X:   hi = g_x_hi;   lo = g_x_lo;   break;
        case AS_XW:  hi = g_xw_hi;  lo = g_xw_lo;  break;
        case AS_E:   hi = g_e_hi;   lo = g_e_lo;   break;
        case AS_H:   hi = g_h_hi;   lo = g_h_lo;   break;
        case AS_HO:  hi = g_ho_hi;  lo = g_ho_lo;  break;
        default:     hi = g_rho_hi; lo = g_rho_lo; break;
    }
}

struct GArgs {
    int aidx[3];
    int woff[3];          // offsets into g_w_hi/lo (GK_STEP2RZ: [0]=w_rh, [1]=w_zh)
    int K[3];
    int shift[3];
    int nph;
    const float* bias;    // GK_E / GK_PRE
    int outId;            // GK_PRE
    float* out2;          // d_out (GK_STEP3)
    int t;
};

// ---------------------------------------------------------------------------
// TF32x3 tensor-core NT GEMM, 64x64 tile, BK=16, 2-stage cp.async pipeline.
// 256 threads = 8 warps as 4(M) x 2(N); warp tile 16x32; MF=1, NF=4.
//   C[m,n] = sum_p sum_k A_p[m - shift_p, k] * W_p[n, k]
// ---------------------------------------------------------------------------
#define BK 16
#define BKP 20
#define BMX 64
#define BNX 64

template <int MODE>
__global__ void __launch_bounds__(256) gemm_t(GArgs g) {
    __shared__ uint32_t Ah[2][BMX][BKP];
    __shared__ uint32_t Al[2][BMX][BKP];
    __shared__ uint32_t Bh[2][BNX][BKP];
    __shared__ uint32_t Bl[2][BNX][BKP];

    const int tid = threadIdx.x;
    const int lane = tid & 31;
    const int warp = tid >> 5;
    const int qr = lane >> 2;   // 0..7
    const int qc = lane & 3;    // 0..3

    const int rowBase = blockIdx.y * BMX;
    const int xblk = (MODE == GK_STEP2RZ) ? (blockIdx.x & 7) : blockIdx.x;
    const int zhalf = (MODE == GK_STEP2RZ) ? (blockIdx.x >> 3) : 0;
    const int colBase = xblk * BNX;

    const int warpM = (warp & 3) * 16;    // 4 warps in M
    const int warpN = (warp >> 2) * 32;   // 2 warps in N

    float acc[4][4];
#pragma unroll
    for (int j = 0; j < 4; j++)
#pragma unroll
        for (int r = 0; r < 4; r++) acc[j][r] = 0.0f;

    // loader: each thread owns one 16B chunk per smem array per stage
    const int lrow = tid >> 2;           // 0..63
    const int lkq = (tid & 3) << 2;      // 0,4,8,12

    for (int p = 0; p < g.nph; p++) {
        const uint32_t *Agh, *Agl;
        a_src(g.aidx[p], Agh, Agl);
        const int wo = (MODE == GK_STEP2RZ) ? g.woff[zhalf] : g.woff[p];
        const uint32_t* __restrict__ Wgh = g_w_hi + wo;
        const uint32_t* __restrict__ Wgl = g_w_lo + wo;
        const int K = g.K[p];
        const int sh = g.shift[p];
        const int NT = K / BK;

        auto load_tile = [&](int kt, int s) {
            const int k0 = kt * BK;
            const int srow = rowBase + lrow - sh;
            const int ok = (srow >= 0) ? 16 : 0;
            const size_t aoff = (srow >= 0) ? ((size_t)srow * K + k0 + lkq) : 0;
            cp16(cvta_s(&Ah[s][lrow][lkq]), Agh + aoff, ok);
            cp16(cvta_s(&Al[s][lrow][lkq]), Agl + aoff, ok);
            const size_t boff = (size_t)(colBase + lrow) * K + k0 + lkq;
            cp16(cvta_s(&Bh[s][lrow][lkq]), Wgh + boff, 16);
            cp16(cvta_s(&Bl[s][lrow][lkq]), Wgl + boff, 16);
        };

        auto compute = [&](int s) {
#pragma unroll
            for (int kk = 0; kk < BK; kk += 8) {
                uint32_t bh0[4], bh1[4], bl0[4], bl1[4];
#pragma unroll
                for (int nf = 0; nf < 4; nf++) {
                    const int brow = warpN + nf * 8 + qr;
                    bh0[nf] = Bh[s][brow][kk + qc];
                    bh1[nf] = Bh[s][brow][kk + qc + 4];
                    bl0[nf] = Bl[s][brow][kk + qc];
                    bl1[nf] = Bl[s][brow][kk + qc + 4];
                }
                const int ar = warpM + qr;
                const uint32_t ah0 = Ah[s][ar][kk + qc];
                const uint32_t ah1 = Ah[s][ar + 8][kk + qc];
                const uint32_t ah2 = Ah[s][ar][kk + qc + 4];
                const uint32_t ah3 = Ah[s][ar + 8][kk + qc + 4];
                const uint32_t al0 = Al[s][ar][kk + qc];
                const uint32_t al1 = Al[s][ar + 8][kk + qc];
                const uint32_t al2 = Al[s][ar][kk + qc + 4];
                const uint32_t al3 = Al[s][ar + 8][kk + qc + 4];
#pragma unroll
                for (int nf = 0; nf < 4; nf++) {
                    mma_tf32(acc[nf], ah0, ah1, ah2, ah3, bh0[nf], bh1[nf]);
                    mma_tf32(acc[nf], al0, al1, al2, al3, bh0[nf], bh1[nf]);
                    mma_tf32(acc[nf], ah0, ah1, ah2, ah3, bl0[nf], bl1[nf]);
                }
            }
        };

        // 2-stage pipeline
        load_tile(0, 0);
        CP_COMMIT();
        for (int kt = 0; kt < NT; kt++) {
            const int cur = kt & 1;
            if (kt + 1 < NT) {
                load_tile(kt + 1, (kt + 1) & 1);
                CP_COMMIT();
                cp_wait<1>();
            } else {
                cp_wait<0>();
            }
            __syncthreads();
            compute(cur);
            __syncthreads();
        }
    }

    // ---- epilogue
    const size_t off = (size_t)g.t * B_ * H_;
#pragma unroll
    for (int nf = 0; nf < 4; nf++) {
#pragma unroll
        for (int r = 0; r < 4; r++) {
            const int m = rowBase + warpM + qr + ((r >= 2) ? 8 : 0);
            const int n = colBase + warpN + nf * 8 + qc * 2 + (r & 1);
            float v = acc[nf][r];
            const size_t idx = (size_t)m * H_ + n;
            if (MODE == GK_E) {
                v += g.bias[n];
                const float e = sigmoidf_(v);
                uint32_t h, l;
                tf32_split(e, h, l);
                g_e_hi[idx] = h;
                g_e_lo[idx] = l;
            } else if (MODE == GK_PRE) {
                if (g.bias) v += g.bias[n];
                const int b_row = m / T_;
                const int t_row = m - b_row * T_;
                scratch_out(g.outId)[((size_t)t_row * B_ + b_row) * H_ + n] = v;
            } else if (MODE == GK_STEP1) {
                v += g_pre_o[off + idx];
                const float ho = sigmoidf_(v);
                g_ho[idx] = ho;
                uint32_t h, l;
                tf32_split(ho, h, l);
                g_ho_hi[idx] = h;
                g_ho_lo[idx] = l;
            } else if (MODE == GK_STEP2RZ) {
                if (zhalf == 0) {
                    v += g_pre_r[off + idx];
                    const float rho = sigmoidf_(v) * g_ho[idx];
                    uint32_t h, l;
                    tf32_split(rho, h, l);
                    g_rho_hi[idx] = h;
                    g_rho_lo[idx] = l;
                } else {
                    v += g_pre_z[off + idx];
                    g_zb[idx] = sigmoidf_(v);
                }
            } else {  // GK_STEP3
                v += g_pre_h[off + idx];
                const float ht = tanhf(v);
                const float z = g_zb[idx];
                const float ho = g_ho[idx];
                const float hcur = (1.0f - z) * ho + z * ht;
                uint32_t h, l;
                tf32_split(hcur, h, l);
                g_h_hi[idx] = h;
                g_h_lo[idx] = l;
                g.out2[((size_t)m * T_ + g.t) * H_ + n] = hcur;
            }
        }
    }
}

// ---------------------------------------------------------------------------
// Host launch — kernel launches ONLY.
// ---------------------------------------------------------------------------
extern "C" void kernel_launch(void* const* d_in, const int* in_sizes, int n_in,
                              void* d_out, int out_size) {
    (void)in_sizes; (void)n_in; (void)out_size;

    const float* x    = (const float*)d_in[0];
    const float* xw   = (const float*)d_in[1];
    const float* w_rx = (const float*)d_in[2];
    const float* w_rh = (const float*)d_in[3];
    const float* w_re = (const float*)d_in[4];
    const float* b_r  = (const float*)d_in[5];
    const float* w_zx = (const float*)d_in[6];
    const float* w_zh = (const float*)d_in[7];
    const float* w_ze = (const float*)d_in[8];
    const float* b_z  = (const float*)d_in[9];
    const float* w_hx = (const float*)d_in[10];
    const float* w_hh = (const float*)d_in[11];
    const float* b_h  = (const float*)d_in[12];
    const float* w_d  = (const float*)d_in[13];
    const float* w_w  = (const float*)d_in[14];
    const float* w_m  = (const float*)d_in[15];
    const float* w_t  = (const float*)d_in[16];
    const float* w_e  = (const float*)d_in[17];
    const float* b_e  = (const float*)d_in[18];
    float* out = (float*)d_out;

    const dim3 blk(256);

    // ---- split all weights + x + xw into tf32 hi/lo buffers
    {
        SplitWArgs a = {};
        const float* srcs[13] = {w_e, w_rx, w_zx, w_hx, w_d, w_w, w_m,
                                 w_re, w_ze, w_rh, w_zh, w_hh, w_t};
        const int szs[13] = {SZ_WE, SZ_HI, SZ_HI, SZ_HI, SZ_HI, SZ_HI, SZ_HI,
                             SZ_HH, SZ_HH, SZ_HH, SZ_HH, SZ_HH, SZ_HH};
        const int offs[13] = {OFF_WE, OFF_WRX, OFF_WZX, OFF_WHX, OFF_WD, OFF_WW,
                              OFF_WM, OFF_WRE, OFF_WZE, OFF_WRH, OFF_WZH,
                              OFF_WHH, OFF_WT};
        for (int i = 0; i < 13; i++) { a.src[i] = srcs[i]; a.sz[i] = szs[i]; a.off[i] = offs[i]; }
        split_w_k<<<dim3(128, 13), blk>>>(a);
        split_x_k<<<dim3(512, 2), blk>>>(x, xw);
    }

    const dim3 gridPre(H_ / BNX, BT_ / BMX);      // 8 x 1536
    const dim3 gridStep(H_ / BNX, B_ / BMX);      // 8 x 64
    const dim3 gridStepRZ(2 * (H_ / BNX), B_ / BMX);  // 16 x 64

    // ---- e = sigmoid(xw @ w_e^T + b_e) -> g_e_hi/lo
    {
        GArgs a = {};
        a.aidx[0] = AS_XW; a.woff[0] = OFF_WE; a.K[0] = W_; a.shift[0] = 0;
        a.nph = 1; a.bias = b_e;
        gemm_t<GK_E><<<gridPre, blk>>>(a);
    }
    // ---- pre_r = x @ w_rx^T + e @ w_re^T + b_r -> g_pre_r [T,B,H]
    {
        GArgs a = {};
        a.aidx[0] = AS_X; a.woff[0] = OFF_WRX; a.K[0] = I_; a.shift[0] = 0;
        a.aidx[1] = AS_E; a.woff[1] = OFF_WRE; a.K[1] = H_; a.shift[1] = 0;
        a.nph = 2; a.bias = b_r; a.outId = SID_PRE_R;
        gemm_t<GK_PRE><<<gridPre, blk>>>(a);
    }
    // ---- pre_z = x @ w_zx^T + e @ w_ze^T + b_z -> g_pre_z [T,B,H]
    {
        GArgs a = {};
        a.aidx[0] = AS_X; a.woff[0] = OFF_WZX; a.K[0] = I_; a.shift[0] = 0;
        a.aidx[1] = AS_E; a.woff[1] = OFF_WZE; a.K[1] = H_; a.shift[1] = 0;
        a.nph = 2; a.bias = b_z; a.outId = SID_PRE_Z;
        gemm_t<GK_PRE><<<gridPre, blk>>>(a);
    }
    // ---- pre_h = x @ w_hx^T + b_h -> g_pre_h [T,B,H]
    {
        GArgs a = {};
        a.aidx[0] = AS_X; a.woff[0] = OFF_WHX; a.K[0] = I_; a.shift[0] = 0;
        a.nph = 1; a.bias = b_h; a.outId = SID_PRE_H;
        gemm_t<GK_PRE><<<gridPre, blk>>>(a);
    }
    // ---- pre_o = shift1(x)@w_d^T + shift7(x)@w_w^T + shift30(x)@w_m^T -> g_pre_o
    //      (batch-axis shifts: row m sources row m - k*T)
    {
        GArgs a = {};
        a.aidx[0] = AS_X; a.woff[0] = OFF_WD; a.K[0] = I_; a.shift[0] = 1 * T_;
        a.aidx[1] = AS_X; a.woff[1] = OFF_WW; a.K[1] = I_; a.shift[1] = 7 * T_;
        a.aidx[2] = AS_X; a.woff[2] = OFF_WM; a.K[2] = I_; a.shift[2] = 30 * T_;
        a.nph = 3; a.outId = SID_PRE_O;
        gemm_t<GK_PRE><<<gridPre, blk>>>(a);
    }

    // ---- recurrence over T steps (3 launches per step)
    for (int t = 0; t < T_; t++) {
        // h_o = sigmoid(pre_o_t + h @ w_t^T); t=0 h=0 via shift=B_ zero-fill
        {
            GArgs a = {};
            a.aidx[0] = AS_H; a.woff[0] = OFF_WT; a.K[0] = H_;
            a.shift[0] = (t == 0) ? B_ : 0;
            a.nph = 1; a.t = t;
            gemm_t<GK_STEP1><<<gridStep, blk>>>(a);
        }
        // fused r | z:  blocks x<8: r*h_o = sig(pre_r + h_o@w_rh^T)*h_o
        //               blocks x>=8: z = sig(pre_z + h_o@w_zh^T)
        {
            GArgs a = {};
            a.aidx[0] = AS_HO;
            a.woff[0] = OFF_WRH; a.woff[1] = OFF_WZH;
            a.K[0] = H_; a.shift[0] = 0;
            a.nph = 1; a.t = t;
            gemm_t<GK_STEP2RZ><<<gridStepRZ, blk>>>(a);
        }
        // h = (1-z)*h_o + z*tanh(pre_h + (r*h_o)@w_hh^T) -> g_h_hi/lo, d_out
        {
            GArgs a = {};
            a.aidx[0] = AS_RHO; a.woff[0] = OFF_WHH; a.K[0] = H_; a.shift[0] = 0;
            a.nph = 1; a.t = t; a.out2 = out;
            gemm_t<GK_STEP3><<<gridStep, blk>>>(a);
        }
    }
}

// round 9
// speedup vs baseline: 2.2030x; 1.7245x over previous
#include <cuda_runtime.h>
#include <cstddef>
#include <cstdint>

// Problem constants
#define B_ 4096
#define T_ 24
#define I_ 128
#define H_ 512
#define W_ 32
#define BT_ (B_ * T_)

// ---------------------------------------------------------------------------
// Weight split-buffer segment offsets (elements)
// ---------------------------------------------------------------------------
#define SZ_WE   (H_ * W_)
#define SZ_HI   (H_ * I_)
#define SZ_HH   (H_ * H_)
#define OFF_WE  0
#define OFF_WRX (OFF_WE  + SZ_WE)
#define OFF_WZX (OFF_WRX + SZ_HI)
#define OFF_WHX (OFF_WZX + SZ_HI)
#define OFF_WD  (OFF_WHX + SZ_HI)
#define OFF_WW  (OFF_WD  + SZ_HI)
#define OFF_WM  (OFF_WW  + SZ_HI)
#define OFF_WRE (OFF_WM  + SZ_HI)
#define OFF_WZE (OFF_WRE + SZ_HH)
#define OFF_WRH (OFF_WZE + SZ_HH)
#define OFF_WZH (OFF_WRH + SZ_HH)
#define OFF_WHH (OFF_WZH + SZ_HH)
#define OFF_WT  (OFF_WHH + SZ_HH)
#define W_TOTAL (OFF_WT  + SZ_HH)

// ---------------------------------------------------------------------------
// Scratch: __device__ globals only. hi/lo = bf16 split planes (uint16).
// ---------------------------------------------------------------------------
__device__ uint16_t g_w_hi[W_TOTAL];
__device__ uint16_t g_w_lo[W_TOTAL];
__device__ uint16_t g_x_hi [(size_t)BT_ * I_];
__device__ uint16_t g_x_lo [(size_t)BT_ * I_];
__device__ uint16_t g_xw_hi[(size_t)BT_ * W_];
__device__ uint16_t g_xw_lo[(size_t)BT_ * W_];
__device__ uint16_t g_e_hi [(size_t)BT_ * H_];
__device__ uint16_t g_e_lo [(size_t)BT_ * H_];
__device__ uint16_t g_h_hi [(size_t)B_ * H_];
__device__ uint16_t g_h_lo [(size_t)B_ * H_];
__device__ uint16_t g_ho_hi[(size_t)B_ * H_];
__device__ uint16_t g_ho_lo[(size_t)B_ * H_];
__device__ uint16_t g_rho_hi[(size_t)B_ * H_];
__device__ uint16_t g_rho_lo[(size_t)B_ * H_];

__device__ float g_pre_o[(size_t)BT_ * H_];   // [T, B, H]
__device__ float g_pre_r[(size_t)BT_ * H_];   // [T, B, H]
__device__ float g_pre_z[(size_t)BT_ * H_];   // [T, B, H]
__device__ float g_pre_h[(size_t)BT_ * H_];   // [T, B, H]
__device__ float g_ho [(size_t)B_ * H_];      // fp32 h_o (epilogue consumer)
__device__ float g_zb [(size_t)B_ * H_];      // fp32 z

// ---------------------------------------------------------------------------
// Helpers
// ---------------------------------------------------------------------------
__device__ __forceinline__ float sigmoidf_(float x) {
    return 1.0f / (1.0f + __expf(-x));
}
__device__ __forceinline__ uint16_t f2bf(float x) {
    uint16_t r;
    asm("cvt.rn.bf16.f32 %0, %1;" : "=h"(r) : "f"(x));
    return r;
}
__device__ __forceinline__ float bf2f(uint16_t h) {
    return __uint_as_float(((uint32_t)h) << 16);
}
__device__ __forceinline__ void bf16_split(float x, uint16_t& hi, uint16_t& lo) {
    hi = f2bf(x);
    lo = f2bf(x - bf2f(hi));
}
__device__ __forceinline__ void mma_bf16(float c[4],
                                         uint32_t a0, uint32_t a1, uint32_t a2, uint32_t a3,
                                         uint32_t b0, uint32_t b1) {
    asm volatile(
        "mma.sync.aligned.m16n8k16.row.col.f32.bf16.bf16.f32 "
        "{%0,%1,%2,%3}, {%4,%5,%6,%7}, {%8,%9}, {%0,%1,%2,%3};"
        : "+f"(c[0]), "+f"(c[1]), "+f"(c[2]), "+f"(c[3])
        : "r"(a0), "r"(a1), "r"(a2), "r"(a3), "r"(b0), "r"(b1));
}
__device__ __forceinline__ uint32_t cvta_s(const void* p) {
    return (uint32_t)__cvta_generic_to_shared(p);
}
__device__ __forceinline__ void cp16(uint32_t saddr, const void* gaddr, int src_bytes) {
    asm volatile("cp.async.ca.shared.global [%0], [%1], 16, %2;"
                 :: "r"(saddr), "l"(gaddr), "r"(src_bytes));
}
#define CP_COMMIT() asm volatile("cp.async.commit_group;")
template <int N>
__device__ __forceinline__ void cp_wait() {
    asm volatile("cp.async.wait_group %0;" :: "n"(N));
}

// ---------------------------------------------------------------------------
// Split kernels
// ---------------------------------------------------------------------------
struct SplitWArgs {
    const float* src[13];
    int sz[13];
    int off[13];
};
__global__ void split_w_k(SplitWArgs a) {
    const int seg = blockIdx.y;
    const int n = a.sz[seg];
    const float* __restrict__ s = a.src[seg];
    const int off = a.off[seg];
    for (int i = blockIdx.x * blockDim.x + threadIdx.x; i < n;
         i += gridDim.x * blockDim.x) {
        uint16_t h, l;
        bf16_split(s[i], h, l);
        g_w_hi[off + i] = h;
        g_w_lo[off + i] = l;
    }
}
__global__ void split_x_k(const float* __restrict__ x, const float* __restrict__ xw) {
    if (blockIdx.y == 0) {
        const size_t n = (size_t)BT_ * I_;
        for (size_t i = blockIdx.x * blockDim.x + threadIdx.x; i < n;
             i += (size_t)gridDim.x * blockDim.x) {
            uint16_t h, l;
            bf16_split(x[i], h, l);
            g_x_hi[i] = h;
            g_x_lo[i] = l;
        }
    } else {
        const size_t n = (size_t)BT_ * W_;
        for (size_t i = blockIdx.x * blockDim.x + threadIdx.x; i < n;
             i += (size_t)gridDim.x * blockDim.x) {
            uint16_t h, l;
            bf16_split(xw[i], h, l);
            g_xw_hi[i] = h;
            g_xw_lo[i] = l;
        }
    }
}

// ---------------------------------------------------------------------------
// GEMM modes / args
// ---------------------------------------------------------------------------
enum { GK_E = 0, GK_PRE = 1, GK_STEP1 = 2, GK_STEP2RZ = 3, GK_STEP3 = 4 };
enum { AS_X = 0, AS_XW = 1, AS_E = 2, AS_H = 3, AS_HO = 4, AS_RHO = 5 };
#define SID_PRE_O 0
#define SID_PRE_R 1
#define SID_PRE_Z 2
#define SID_PRE_H 3

__device__ __forceinline__ float* scratch_out(int id) {
    switch (id) {
        case SID_PRE_O: return g_pre_o;
        case SID_PRE_R: return g_pre_r;
        case SID_PRE_Z: return g_pre_z;
        default:        return g_pre_h;
    }
}
__device__ __forceinline__ void a_src(int id, const uint16_t*& hi, const uint16_t*& lo) {
    switch (id) {
        case AS_X:   hi = g_x_hi;   lo = g_x_lo;   break;
        case AS_XW:  hi = g_xw_hi;  lo = g_xw_lo;  break;
        case AS_E:   hi = g_e_hi;   lo = g_e_lo;   break;
        case AS_H:   hi = g_h_hi;   lo = g_h_lo;   break;
        case AS_HO:  hi = g_ho_hi;  lo = g_ho_lo;  break;
        default:     hi = g_rho_hi; lo = g_rho_lo; break;
    }
}

struct GArgs {
    int aidx[3];
    int woff[3];          // offsets into g_w_hi/lo (GK_STEP2RZ: [0]=w_rh, [1]=w_zh)
    int K[3];
    int shift[3];
    int nph;
    const float* bias;    // GK_E / GK_PRE
    int outId;            // GK_PRE
    float* out2;          // d_out (GK_STEP3)
    int t;
};

// ---------------------------------------------------------------------------
// BF16x3 tensor-core NT GEMM, 64x64 tile, BK=32 elems, 2-stage cp.async.
// 256 threads = 8 warps as 4(M) x 2(N); warp tile 16x32 (MF=1, NF=4).
//   C[m,n] = sum_p sum_k A_p[m - shift_p, k] * W_p[n, k]
// Accuracy: hi*hi + lo*hi + hi*lo (drops only lo*lo ~ 2^-16 relative).
// ---------------------------------------------------------------------------
#define BK 32
#define BKP 40   // padded bf16 entries per row (bank-conflict-free)
#define BMX 64
#define BNX 64

template <int MODE>
__global__ void __launch_bounds__(256) gemm_t(GArgs g) {
    __shared__ uint16_t Ah[2][BMX][BKP];
    __shared__ uint16_t Al[2][BMX][BKP];
    __shared__ uint16_t Bh[2][BNX][BKP];
    __shared__ uint16_t Bl[2][BNX][BKP];

    const int tid = threadIdx.x;
    const int lane = tid & 31;
    const int warp = tid >> 5;
    const int qr = lane >> 2;   // 0..7
    const int qc = lane & 3;    // 0..3

    const int rowBase = blockIdx.y * BMX;
    const int xblk = (MODE == GK_STEP2RZ) ? (blockIdx.x & 7) : blockIdx.x;
    const int zhalf = (MODE == GK_STEP2RZ) ? (blockIdx.x >> 3) : 0;
    const int colBase = xblk * BNX;

    const int warpM = (warp & 3) * 16;    // 4 warps in M
    const int warpN = (warp >> 2) * 32;   // 2 warps in N

    float acc[4][4];
#pragma unroll
    for (int j = 0; j < 4; j++)
#pragma unroll
        for (int r = 0; r < 4; r++) acc[j][r] = 0.0f;

    // loader: 64 rows x 4 chunks of 16B (8 bf16) = 256 thread-chunks
    const int lrow = tid >> 2;           // 0..63
    const int lkq = (tid & 3) << 3;      // 0,8,16,24 (bf16 elements)

    for (int p = 0; p < g.nph; p++) {
        const uint16_t *Agh, *Agl;
        a_src(g.aidx[p], Agh, Agl);
        const int wo = (MODE == GK_STEP2RZ) ? g.woff[zhalf] : g.woff[p];
        const uint16_t* __restrict__ Wgh = g_w_hi + wo;
        const uint16_t* __restrict__ Wgl = g_w_lo + wo;
        const int K = g.K[p];
        const int sh = g.shift[p];
        const int NT = K / BK;

        auto load_tile = [&](int kt, int s) {
            const int k0 = kt * BK;
            const int srow = rowBase + lrow - sh;
            const int ok = (srow >= 0) ? 16 : 0;
            const size_t aoff = (srow >= 0) ? ((size_t)srow * K + k0 + lkq) : 0;
            cp16(cvta_s(&Ah[s][lrow][lkq]), Agh + aoff, ok);
            cp16(cvta_s(&Al[s][lrow][lkq]), Agl + aoff, ok);
            const size_t boff = (size_t)(colBase + lrow) * K + k0 + lkq;
            cp16(cvta_s(&Bh[s][lrow][lkq]), Wgh + boff, 16);
            cp16(cvta_s(&Bl[s][lrow][lkq]), Wgl + boff, 16);
        };

        auto compute = [&](int s) {
#pragma unroll
            for (int kk = 0; kk < BK; kk += 16) {
                const int kc = kk + 2 * qc;
                uint32_t bh0[4], bh1[4], bl0[4], bl1[4];
#pragma unroll
                for (int nf = 0; nf < 4; nf++) {
                    const int brow = warpN + nf * 8 + qr;
                    bh0[nf] = *reinterpret_cast<const uint32_t*>(&Bh[s][brow][kc]);
                    bh1[nf] = *reinterpret_cast<const uint32_t*>(&Bh[s][brow][kc + 8]);
                    bl0[nf] = *reinterpret_cast<const uint32_t*>(&Bl[s][brow][kc]);
                    bl1[nf] = *reinterpret_cast<const uint32_t*>(&Bl[s][brow][kc + 8]);
                }
                const int ar = warpM + qr;
                const uint32_t ah0 = *reinterpret_cast<const uint32_t*>(&Ah[s][ar][kc]);
                const uint32_t ah1 = *reinterpret_cast<const uint32_t*>(&Ah[s][ar + 8][kc]);
                const uint32_t ah2 = *reinterpret_cast<const uint32_t*>(&Ah[s][ar][kc + 8]);
                const uint32_t ah3 = *reinterpret_cast<const uint32_t*>(&Ah[s][ar + 8][kc + 8]);
                const uint32_t al0 = *reinterpret_cast<const uint32_t*>(&Al[s][ar][kc]);
                const uint32_t al1 = *reinterpret_cast<const uint32_t*>(&Al[s][ar + 8][kc]);
                const uint32_t al2 = *reinterpret_cast<const uint32_t*>(&Al[s][ar][kc + 8]);
                const uint32_t al3 = *reinterpret_cast<const uint32_t*>(&Al[s][ar + 8][kc + 8]);
#pragma unroll
                for (int nf = 0; nf < 4; nf++) {
                    mma_bf16(acc[nf], ah0, ah1, ah2, ah3, bh0[nf], bh1[nf]);
                    mma_bf16(acc[nf], al0, al1, al2, al3, bh0[nf], bh1[nf]);
                    mma_bf16(acc[nf], ah0, ah1, ah2, ah3, bl0[nf], bl1[nf]);
                }
            }
        };

        // 2-stage pipeline
        load_tile(0, 0);
        CP_COMMIT();
        for (int kt = 0; kt < NT; kt++) {
            const int cur = kt & 1;
            if (kt + 1 < NT) {
                load_tile(kt + 1, (kt + 1) & 1);
                CP_COMMIT();
                cp_wait<1>();
            } else {
                cp_wait<0>();
            }
            __syncthreads();
            compute(cur);
            __syncthreads();
        }
    }

    // ---- epilogue
    const size_t off = (size_t)g.t * B_ * H_;
#pragma unroll
    for (int nf = 0; nf < 4; nf++) {
#pragma unroll
        for (int r = 0; r < 4; r++) {
            const int m = rowBase + warpM + qr + ((r >= 2) ? 8 : 0);
            const int n = colBase + warpN + nf * 8 + qc * 2 + (r & 1);
            float v = acc[nf][r];
            const size_t idx = (size_t)m * H_ + n;
            if (MODE == GK_E) {
                v += g.bias[n];
                const float e = sigmoidf_(v);
                uint16_t h, l;
                bf16_split(e, h, l);
                g_e_hi[idx] = h;
                g_e_lo[idx] = l;
            } else if (MODE == GK_PRE) {
                if (g.bias) v += g.bias[n];
                const int b_row = m / T_;
                const int t_row = m - b_row * T_;
                scratch_out(g.outId)[((size_t)t_row * B_ + b_row) * H_ + n] = v;
            } else if (MODE == GK_STEP1) {
                v += g_pre_o[off + idx];
                const float ho = sigmoidf_(v);
                g_ho[idx] = ho;
                uint16_t h, l;
                bf16_split(ho, h, l);
                g_ho_hi[idx] = h;
                g_ho_lo[idx] = l;
            } else if (MODE == GK_STEP2RZ) {
                if (zhalf == 0) {
                    v += g_pre_r[off + idx];
                    const float rho = sigmoidf_(v) * g_ho[idx];
                    uint16_t h, l;
                    bf16_split(rho, h, l);
                    g_rho_hi[idx] = h;
                    g_rho_lo[idx] = l;
                } else {
                    v += g_pre_z[off + idx];
                    g_zb[idx] = sigmoidf_(v);
                }
            } else {  // GK_STEP3
                v += g_pre_h[off + idx];
                const float ht = tanhf(v);
                const float z = g_zb[idx];
                const float ho = g_ho[idx];
                const float hcur = (1.0f - z) * ho + z * ht;
                uint16_t h, l;
                bf16_split(hcur, h, l);
                g_h_hi[idx] = h;
                g_h_lo[idx] = l;
                g.out2[((size_t)m * T_ + g.t) * H_ + n] = hcur;
            }
        }
    }
}

// ---------------------------------------------------------------------------
// Host launch — kernel launches ONLY.
// ---------------------------------------------------------------------------
extern "C" void kernel_launch(void* const* d_in, const int* in_sizes, int n_in,
                              void* d_out, int out_size) {
    (void)in_sizes; (void)n_in; (void)out_size;

    const float* x    = (const float*)d_in[0];
    const float* xw   = (const float*)d_in[1];
    const float* w_rx = (const float*)d_in[2];
    const float* w_rh = (const float*)d_in[3];
    const float* w_re = (const float*)d_in[4];
    const float* b_r  = (const float*)d_in[5];
    const float* w_zx = (const float*)d_in[6];
    const float* w_zh = (const float*)d_in[7];
    const float* w_ze = (const float*)d_in[8];
    const float* b_z  = (const float*)d_in[9];
    const float* w_hx = (const float*)d_in[10];
    const float* w_hh = (const float*)d_in[11];
    const float* b_h  = (const float*)d_in[12];
    const float* w_d  = (const float*)d_in[13];
    const float* w_w  = (const float*)d_in[14];
    const float* w_m  = (const float*)d_in[15];
    const float* w_t  = (const float*)d_in[16];
    const float* w_e  = (const float*)d_in[17];
    const float* b_e  = (const float*)d_in[18];
    float* out = (float*)d_out;

    const dim3 blk(256);

    // ---- split all weights + x + xw into bf16 hi/lo planes
    {
        SplitWArgs a = {};
        const float* srcs[13] = {w_e, w_rx, w_zx, w_hx, w_d, w_w, w_m,
                                 w_re, w_ze, w_rh, w_zh, w_hh, w_t};
        const int szs[13] = {SZ_WE, SZ_HI, SZ_HI, SZ_HI, SZ_HI, SZ_HI, SZ_HI,
                             SZ_HH, SZ_HH, SZ_HH, SZ_HH, SZ_HH, SZ_HH};
        const int offs[13] = {OFF_WE, OFF_WRX, OFF_WZX, OFF_WHX, OFF_WD, OFF_WW,
                              OFF_WM, OFF_WRE, OFF_WZE, OFF_WRH, OFF_WZH,
                              OFF_WHH, OFF_WT};
        for (int i = 0; i < 13; i++) { a.src[i] = srcs[i]; a.sz[i] = szs[i]; a.off[i] = offs[i]; }
        split_w_k<<<dim3(128, 13), blk>>>(a);
        split_x_k<<<dim3(512, 2), blk>>>(x, xw);
    }

    const dim3 gridPre(H_ / BNX, BT_ / BMX);          // 8 x 1536
    const dim3 gridStep(H_ / BNX, B_ / BMX);          // 8 x 64
    const dim3 gridStepRZ(2 * (H_ / BNX), B_ / BMX);  // 16 x 64

    // ---- e = sigmoid(xw @ w_e^T + b_e) -> g_e_hi/lo
    {
        GArgs a = {};
        a.aidx[0] = AS_XW; a.woff[0] = OFF_WE; a.K[0] = W_; a.shift[0] = 0;
        a.nph = 1; a.bias = b_e;
        gemm_t<GK_E><<<gridPre, blk>>>(a);
    }
    // ---- pre_r = x @ w_rx^T + e @ w_re^T + b_r -> g_pre_r [T,B,H]
    {
        GArgs a = {};
        a.aidx[0] = AS_X; a.woff[0] = OFF_WRX; a.K[0] = I_; a.shift[0] = 0;
        a.aidx[1] = AS_E; a.woff[1] = OFF_WRE; a.K[1] = H_; a.shift[1] = 0;
        a.nph = 2; a.bias = b_r; a.outId = SID_PRE_R;
        gemm_t<GK_PRE><<<gridPre, blk>>>(a);
    }
    // ---- pre_z = x @ w_zx^T + e @ w_ze^T + b_z -> g_pre_z [T,B,H]
    {
        GArgs a = {};
        a.aidx[0] = AS_X; a.woff[0] = OFF_WZX; a.K[0] = I_; a.shift[0] = 0;
        a.aidx[1] = AS_E; a.woff[1] = OFF_WZE; a.K[1] = H_; a.shift[1] = 0;
        a.nph = 2; a.bias = b_z; a.outId = SID_PRE_Z;
        gemm_t<GK_PRE><<<gridPre, blk>>>(a);
    }
    // ---- pre_h = x @ w_hx^T + b_h -> g_pre_h [T,B,H]
    {
        GArgs a = {};
        a.aidx[0] = AS_X; a.woff[0] = OFF_WHX; a.K[0] = I_; a.shift[0] = 0;
        a.nph = 1; a.bias = b_h; a.outId = SID_PRE_H;
        gemm_t<GK_PRE><<<gridPre, blk>>>(a);
    }
    // ---- pre_o = shift1(x)@w_d^T + shift7(x)@w_w^T + shift30(x)@w_m^T -> g_pre_o
    //      (batch-axis shifts: row m sources row m - k*T)
    {
        GArgs a = {};
        a.aidx[0] = AS_X; a.woff[0] = OFF_WD; a.K[0] = I_; a.shift[0] = 1 * T_;
        a.aidx[1] = AS_X; a.woff[1] = OFF_WW; a.K[1] = I_; a.shift[1] = 7 * T_;
        a.aidx[2] = AS_X; a.woff[2] = OFF_WM; a.K[2] = I_; a.shift[2] = 30 * T_;
        a.nph = 3; a.outId = SID_PRE_O;
        gemm_t<GK_PRE><<<gridPre, blk>>>(a);
    }

    // ---- recurrence over T steps (3 launches per step)
    for (int t = 0; t < T_; t++) {
        // h_o = sigmoid(pre_o_t + h @ w_t^T); t=0 h=0 via shift=B_ zero-fill
        {
            GArgs a = {};
            a.aidx[0] = AS_H; a.woff[0] = OFF_WT; a.K[0] = H_;
            a.shift[0] = (t == 0) ? B_ : 0;
            a.nph = 1; a.t = t;
            gemm_t<GK_STEP1><<<gridStep, blk>>>(a);
        }
        // fused r | z:  blocks x<8: r*h_o = sig(pre_r + h_o@w_rh^T)*h_o
        //               blocks x>=8: z = sig(pre_z + h_o@w_zh^T)
        {
            GArgs a = {};
            a.aidx[0] = AS_HO;
            a.woff[0] = OFF_WRH; a.woff[1] = OFF_WZH;
            a.K[0] = H_; a.shift[0] = 0;
            a.nph = 1; a.t = t;
            gemm_t<GK_STEP2RZ><<<gridStepRZ, blk>>>(a);
        }
        // h = (1-z)*h_o + z*tanh(pre_h + (r*h_o)@w_hh^T) -> g_h_hi/lo, d_out
        {
            GArgs a = {};
            a.aidx[0] = AS_RHO; a.woff[0] = OFF_WHH; a.K[0] = H_; a.shift[0] = 0;
            a.nph = 1; a.t = t; a.out2 = out;
            gemm_t<GK_STEP3><<<gridStep, blk>>>(a);
        }
    }
}